// round 9
// baseline (speedup 1.0000x reference)
#include <cuda_runtime.h>

// CoralFocalLoss multi-task reduction via piecewise-linear tables:
//   half 0 (tm=1): f0(x) = 0.25 * phi(x)
//   half 1 (tm=0): f1(x) = 0.75 * phi(-x)
// where phi(u) = -(1-sigmoid(u))^2 * log(sigmoid(u) + 1e-8).
// Element loss = f_{tm}(x), weighted by class_weights[kl_t]; tm = (col < target).

#define NSEG      1536              // segments per half, x in [-12,12), h=1/64
#define TBL_TOTAL (2 * NSEG)
#define NBLK      592
#define NTHR      256

__device__ float2 g_tbl[TBL_TOTAL];
__device__ double g_acc[3];

__device__ __forceinline__ double phi_ref(double u) {
    double p = 1.0 / (1.0 + exp(-u));
    double q = 1.0 - p;
    return -q * q * log(p + 1e-8);
}

__global__ void init_kernel() {
    int idx = blockIdx.x * blockDim.x + threadIdx.x;
    if (idx < 3) g_acc[idx] = 0.0;
    if (idx >= TBL_TOTAL) return;
    int  half = (idx >= NSEG) ? 1 : 0;
    int  seg  = half ? (idx - NSEG) : idx;
    const double h = 1.0 / 64.0;
    double x0 = -12.0 + seg * h;
    double x1 = x0 + h;
    double y0, y1;
    if (half == 0) { y0 = 0.25 * phi_ref(x0);  y1 = 0.25 * phi_ref(x1); }
    else           { y0 = 0.75 * phi_ref(-x0); y1 = 0.75 * phi_ref(-x1); }
    double slope = (y1 - y0) * 64.0;          // chord slope in x
    double inter = y0 - slope * x0;           // val = slope*x + inter
    g_tbl[idx] = make_float2((float)slope, (float)inter);
}

// C = 768 for half 0 (tm=1), 2304 for half 1 (tm=0); index = 64*x + C
__device__ __forceinline__ float tbl_eval(const float2* __restrict__ t,
                                          float x, float C) {
    float fi = fmaf(x, 64.0f, C);
    int   i  = (int)fi;
    i = min(max(i, 0), TBL_TOTAL - 1);        // OOD guard, branch-free
    float2 e = t[i];
    return fmaf(x, e.x, e.y);
}

__global__ void __launch_bounds__(NTHR)
loss_kernel(const float4* __restrict__ kl4,
            const float*  __restrict__ jm,
            const float*  __restrict__ jl,
            const float*  __restrict__ cw,
            const int*    __restrict__ kt_,
            const int*    __restrict__ mt_,
            const int*    __restrict__ lt_,
            int n) {
    __shared__ float2 s_tbl[TBL_TOTAL];
    __shared__ float  s_cw[5];
    __shared__ float4 s_c5[5];                // per kl-target table-base consts (4 cols)
    __shared__ float4 s_c4[4];                // per jsn-target (3 cols used)
    __shared__ float  s_red[3][NTHR / 32];

    for (int i = threadIdx.x; i < TBL_TOTAL; i += NTHR)
        s_tbl[i] = g_tbl[i];
    if (threadIdx.x < 5) {
        int k = threadIdx.x;
        s_cw[k] = cw[k];
        float4 c;
        c.x = (0 < k) ? 768.f : 2304.f;
        c.y = (1 < k) ? 768.f : 2304.f;
        c.z = (2 < k) ? 768.f : 2304.f;
        c.w = (3 < k) ? 768.f : 2304.f;
        s_c5[k] = c;
        if (k < 4) s_c4[k] = c;
    }
    __syncthreads();

    float a0 = 0.f, a1 = 0.f, a2 = 0.f;
    const int stride = gridDim.x * NTHR;
    #pragma unroll 4
    for (int i = blockIdx.x * NTHR + threadIdx.x; i < n; i += stride) {
        int kt = kt_[i];
        int mt = mt_[i];
        int lt = lt_[i];
        float4 x = kl4[i];
        float m0 = jm[3 * i], m1 = jm[3 * i + 1], m2 = jm[3 * i + 2];
        float l0 = jl[3 * i], l1 = jl[3 * i + 1], l2 = jl[3 * i + 2];

        float4 cc = s_c5[kt];
        float rk;
        rk  = tbl_eval(s_tbl, x.x, cc.x);
        rk += tbl_eval(s_tbl, x.y, cc.y);
        rk += tbl_eval(s_tbl, x.z, cc.z);
        rk += tbl_eval(s_tbl, x.w, cc.w);

        cc = s_c4[mt];
        float rm;
        rm  = tbl_eval(s_tbl, m0, cc.x);
        rm += tbl_eval(s_tbl, m1, cc.y);
        rm += tbl_eval(s_tbl, m2, cc.z);

        cc = s_c4[lt];
        float rl;
        rl  = tbl_eval(s_tbl, l0, cc.x);
        rl += tbl_eval(s_tbl, l1, cc.y);
        rl += tbl_eval(s_tbl, l2, cc.z);

        float w = s_cw[kt];
        a0 = fmaf(w, rk, a0);
        a1 = fmaf(w, rm, a1);
        a2 = fmaf(w, rl, a2);
    }

    // warp reduce
    #pragma unroll
    for (int off = 16; off > 0; off >>= 1) {
        a0 += __shfl_down_sync(0xFFFFFFFFu, a0, off);
        a1 += __shfl_down_sync(0xFFFFFFFFu, a1, off);
        a2 += __shfl_down_sync(0xFFFFFFFFu, a2, off);
    }
    int lane = threadIdx.x & 31;
    int wid  = threadIdx.x >> 5;
    if (lane == 0) {
        s_red[0][wid] = a0;
        s_red[1][wid] = a1;
        s_red[2][wid] = a2;
    }
    __syncthreads();
    if (wid == 0) {
        const int nw = NTHR / 32;
        a0 = (lane < nw) ? s_red[0][lane] : 0.f;
        a1 = (lane < nw) ? s_red[1][lane] : 0.f;
        a2 = (lane < nw) ? s_red[2][lane] : 0.f;
        #pragma unroll
        for (int off = nw / 2; off > 0; off >>= 1) {
            a0 += __shfl_down_sync(0xFFFFFFFFu, a0, off);
            a1 += __shfl_down_sync(0xFFFFFFFFu, a1, off);
            a2 += __shfl_down_sync(0xFFFFFFFFu, a2, off);
        }
        if (lane == 0) {
            atomicAdd(&g_acc[0], (double)a0);
            atomicAdd(&g_acc[1], (double)a1);
            atomicAdd(&g_acc[2], (double)a2);
        }
    }
}

__global__ void finalize_kernel(float* out, int n, int out_size) {
    if (threadIdx.x == 0 && blockIdx.x == 0) {
        double lkl = g_acc[0] / (4.0 * (double)n);
        double lm  = g_acc[1] / (3.0 * (double)n);
        double ll  = g_acc[2] / (3.0 * (double)n);
        double tot = (lkl + lm + ll) / 3.0;
        if (out_size > 0) out[0] = (float)tot;
        if (out_size > 1) out[1] = (float)lkl;
        if (out_size > 2) out[2] = (float)lm;
        if (out_size > 3) out[3] = (float)ll;
    }
}

extern "C" void kernel_launch(void* const* d_in, const int* in_sizes, int n_in,
                              void* d_out, int out_size) {
    const float4* kl4 = (const float4*)d_in[0];   // [N,4] f32
    const float*  jm  = (const float*)d_in[1];    // [N,3] f32
    const float*  jl  = (const float*)d_in[2];    // [N,3] f32
    const float*  cw  = (const float*)d_in[3];    // [5]   f32
    const int*    kt  = (const int*)d_in[4];      // [N]   i32
    const int*    mt  = (const int*)d_in[5];      // [N]   i32
    const int*    lt  = (const int*)d_in[6];      // [N]   i32
    int n = in_sizes[4];

    init_kernel<<<(TBL_TOTAL + 255) / 256, 256>>>();
    loss_kernel<<<NBLK, NTHR>>>(kl4, jm, jl, cw, kt, mt, lt, n);
    finalize_kernel<<<1, 32>>>((float*)d_out, n, out_size);
}

// round 12
// speedup vs baseline: 1.2521x; 1.2521x over previous
#include <cuda_runtime.h>

// CoralFocalLoss multi-task reduction via piecewise-linear tables:
//   half 0 (tm=1): f0(x) = 0.25 * phi(x)
//   half 1 (tm=0): f1(x) = 0.75 * phi(-x)
// where phi(u) = -(1-sigmoid(u))^2 * log(sigmoid(u) + 1e-8).
// Element loss = f_{tm}(x), weighted by class_weights[kl_t]; tm = (col < target).
// Final reduction fused into loss_kernel via last-block-done counter.

#define NSEG      1536              // segments per half, x in [-12,12), h=1/64
#define TBL_TOTAL (2 * NSEG)
#define NBLK      592
#define NTHR      256

__device__ float2 g_tbl[TBL_TOTAL];
__device__ double g_acc[3];
__device__ unsigned int g_done;

// float phi: expf/logf are MUFU-backed (fast path).
__device__ __forceinline__ float phi_f(float u) {
    float p = 1.0f / (1.0f + expf(-u));
    float q = 1.0f - p;
    return -q * q * logf(p + 1e-8f);
}

__global__ void init_kernel() {
    int idx = blockIdx.x * blockDim.x + threadIdx.x;
    if (idx < 3) g_acc[idx] = 0.0;
    if (idx == 3) g_done = 0u;
    if (idx >= TBL_TOTAL) return;
    int   half = (idx >= NSEG) ? 1 : 0;
    int   seg  = half ? (idx - NSEG) : idx;
    float w    = half ? 0.75f : 0.25f;
    float sgn  = half ? -1.0f : 1.0f;
    const float h = 1.0f / 64.0f;
    float x0 = -12.0f + seg * h;
    float x1 = x0 + h;
    float y0 = w * phi_f(sgn * x0);
    float y1 = w * phi_f(sgn * x1);
    float slope = (y1 - y0) * 64.0f;          // chord slope in x
    float inter = fmaf(-slope, x0, y0);       // val = slope*x + inter
    g_tbl[idx] = make_float2(slope, inter);
}

// C = 768 for half 0 (tm=1), 2304 for half 1 (tm=0); index = 64*x + C
__device__ __forceinline__ float tbl_eval(const float2* __restrict__ t,
                                          float x, float C) {
    float fi = fmaf(x, 64.0f, C);
    int   i  = (int)fi;
    i = min(max(i, 0), TBL_TOTAL - 1);        // OOD guard, branch-free
    float2 e = t[i];
    return fmaf(x, e.x, e.y);
}

__global__ void __launch_bounds__(NTHR)
loss_kernel(const float4* __restrict__ kl4,
            const float*  __restrict__ jm,
            const float*  __restrict__ jl,
            const float*  __restrict__ cw,
            const int*    __restrict__ kt_,
            const int*    __restrict__ mt_,
            const int*    __restrict__ lt_,
            int n, float* __restrict__ out, int out_size) {
    __shared__ float2 s_tbl[TBL_TOTAL];
    __shared__ float  s_cw[5];
    __shared__ float4 s_c5[5];                // per kl-target table-base consts (4 cols)
    __shared__ float4 s_c4[4];                // per jsn-target (3 cols used)
    __shared__ float  s_red[3][NTHR / 32];

    for (int i = threadIdx.x; i < TBL_TOTAL; i += NTHR)
        s_tbl[i] = g_tbl[i];
    if (threadIdx.x < 5) {
        int k = threadIdx.x;
        s_cw[k] = cw[k];
        float4 c;
        c.x = (0 < k) ? 768.f : 2304.f;
        c.y = (1 < k) ? 768.f : 2304.f;
        c.z = (2 < k) ? 768.f : 2304.f;
        c.w = (3 < k) ? 768.f : 2304.f;
        s_c5[k] = c;
        if (k < 4) s_c4[k] = c;
    }
    __syncthreads();

    float a0 = 0.f, a1 = 0.f, a2 = 0.f;
    const int stride = gridDim.x * NTHR;
    #pragma unroll 4
    for (int i = blockIdx.x * NTHR + threadIdx.x; i < n; i += stride) {
        int kt = kt_[i];
        int mt = mt_[i];
        int lt = lt_[i];
        float4 x = kl4[i];
        float m0 = jm[3 * i], m1 = jm[3 * i + 1], m2 = jm[3 * i + 2];
        float l0 = jl[3 * i], l1 = jl[3 * i + 1], l2 = jl[3 * i + 2];

        float4 cc = s_c5[kt];
        float rk;
        rk  = tbl_eval(s_tbl, x.x, cc.x);
        rk += tbl_eval(s_tbl, x.y, cc.y);
        rk += tbl_eval(s_tbl, x.z, cc.z);
        rk += tbl_eval(s_tbl, x.w, cc.w);

        cc = s_c4[mt];
        float rm;
        rm  = tbl_eval(s_tbl, m0, cc.x);
        rm += tbl_eval(s_tbl, m1, cc.y);
        rm += tbl_eval(s_tbl, m2, cc.z);

        cc = s_c4[lt];
        float rl;
        rl  = tbl_eval(s_tbl, l0, cc.x);
        rl += tbl_eval(s_tbl, l1, cc.y);
        rl += tbl_eval(s_tbl, l2, cc.z);

        float w = s_cw[kt];
        a0 = fmaf(w, rk, a0);
        a1 = fmaf(w, rm, a1);
        a2 = fmaf(w, rl, a2);
    }

    // warp reduce
    #pragma unroll
    for (int off = 16; off > 0; off >>= 1) {
        a0 += __shfl_down_sync(0xFFFFFFFFu, a0, off);
        a1 += __shfl_down_sync(0xFFFFFFFFu, a1, off);
        a2 += __shfl_down_sync(0xFFFFFFFFu, a2, off);
    }
    int lane = threadIdx.x & 31;
    int wid  = threadIdx.x >> 5;
    if (lane == 0) {
        s_red[0][wid] = a0;
        s_red[1][wid] = a1;
        s_red[2][wid] = a2;
    }
    __syncthreads();
    if (wid == 0) {
        const int nw = NTHR / 32;
        a0 = (lane < nw) ? s_red[0][lane] : 0.f;
        a1 = (lane < nw) ? s_red[1][lane] : 0.f;
        a2 = (lane < nw) ? s_red[2][lane] : 0.f;
        #pragma unroll
        for (int off = nw / 2; off > 0; off >>= 1) {
            a0 += __shfl_down_sync(0xFFFFFFFFu, a0, off);
            a1 += __shfl_down_sync(0xFFFFFFFFu, a1, off);
            a2 += __shfl_down_sync(0xFFFFFFFFu, a2, off);
        }
        if (lane == 0) {
            atomicAdd(&g_acc[0], (double)a0);
            atomicAdd(&g_acc[1], (double)a1);
            atomicAdd(&g_acc[2], (double)a2);
            __threadfence();
            unsigned int prev = atomicAdd(&g_done, 1u);
            if (prev == gridDim.x - 1) {
                // last block: all g_acc atomics are visible (fence + atomic order)
                double lkl = g_acc[0] / (4.0 * (double)n);
                double lm  = g_acc[1] / (3.0 * (double)n);
                double ll  = g_acc[2] / (3.0 * (double)n);
                double tot = (lkl + lm + ll) / 3.0;
                if (out_size > 0) out[0] = (float)tot;
                if (out_size > 1) out[1] = (float)lkl;
                if (out_size > 2) out[2] = (float)lm;
                if (out_size > 3) out[3] = (float)ll;
            }
        }
    }
}

extern "C" void kernel_launch(void* const* d_in, const int* in_sizes, int n_in,
                              void* d_out, int out_size) {
    const float4* kl4 = (const float4*)d_in[0];   // [N,4] f32
    const float*  jm  = (const float*)d_in[1];    // [N,3] f32
    const float*  jl  = (const float*)d_in[2];    // [N,3] f32
    const float*  cw  = (const float*)d_in[3];    // [5]   f32
    const int*    kt  = (const int*)d_in[4];      // [N]   i32
    const int*    mt  = (const int*)d_in[5];      // [N]   i32
    const int*    lt  = (const int*)d_in[6];      // [N]   i32
    int n = in_sizes[4];

    init_kernel<<<(TBL_TOTAL + 255) / 256, 256>>>();
    loss_kernel<<<NBLK, NTHR>>>(kl4, jm, jl, cw, kt, mt, lt, n,
                                (float*)d_out, out_size);
}

// round 14
// speedup vs baseline: 1.3047x; 1.0420x over previous
#include <cuda_runtime.h>

// CoralFocalLoss multi-task reduction via piecewise-linear tables:
//   half 0 (tm=1): f0(x) = 0.25 * phi(x)
//   half 1 (tm=0): f1(x) = 0.75 * phi(-x)
// where phi(u) = -(1-sigmoid(u))^2 * log(sigmoid(u) + 1e-8).
// Element loss = f_{tm}(x), weighted by class_weights[kl_t]; tm = (col < target).
// Final reduction fused into loss_kernel via last-block-done counter.

#define NSEG      1536              // segments per half, x in [-12,12), h=1/64
#define TBL_TOTAL (2 * NSEG)
#define NBLK      888               // 148 SMs x 6 CTAs (reg-limited residency), 1 wave
#define NTHR      256

__device__ float2 g_tbl[TBL_TOTAL];
__device__ double g_acc[3];
__device__ unsigned int g_done;

// float phi: expf/logf are MUFU-backed (fast path).
__device__ __forceinline__ float phi_f(float u) {
    float p = 1.0f / (1.0f + expf(-u));
    float q = 1.0f - p;
    return -q * q * logf(p + 1e-8f);
}

__global__ void init_kernel() {
    int idx = blockIdx.x * blockDim.x + threadIdx.x;
    if (idx < 3) g_acc[idx] = 0.0;
    if (idx == 3) g_done = 0u;
    if (idx >= TBL_TOTAL) return;
    int   half = (idx >= NSEG) ? 1 : 0;
    int   seg  = half ? (idx - NSEG) : idx;
    float w    = half ? 0.75f : 0.25f;
    float sgn  = half ? -1.0f : 1.0f;
    const float h = 1.0f / 64.0f;
    float x0 = -12.0f + seg * h;
    float x1 = x0 + h;
    float y0 = w * phi_f(sgn * x0);
    float y1 = w * phi_f(sgn * x1);
    float slope = (y1 - y0) * 64.0f;          // chord slope in x
    float inter = fmaf(-slope, x0, y0);       // val = slope*x + inter
    g_tbl[idx] = make_float2(slope, inter);
}

// C = 768 for half 0 (tm=1), 2304 for half 1 (tm=0); index = 64*x + C
__device__ __forceinline__ float tbl_eval(const float2* __restrict__ t,
                                          float x, float C) {
    float fi = fmaf(x, 64.0f, C);
    int   i  = (int)fi;
    i = min(max(i, 0), TBL_TOTAL - 1);        // OOD guard, branch-free
    float2 e = t[i];
    return fmaf(x, e.x, e.y);
}

__global__ void __launch_bounds__(NTHR, 6)
loss_kernel(const float4* __restrict__ kl4,
            const float*  __restrict__ jm,
            const float*  __restrict__ jl,
            const float*  __restrict__ cw,
            const int*    __restrict__ kt_,
            const int*    __restrict__ mt_,
            const int*    __restrict__ lt_,
            int n, float* __restrict__ out, int out_size) {
    __shared__ float2 s_tbl[TBL_TOTAL];
    __shared__ float  s_cw[5];
    __shared__ float4 s_c5[5];                // per kl-target table-base consts (4 cols)
    __shared__ float4 s_c4[4];                // per jsn-target (3 cols used)
    __shared__ float  s_red[3][NTHR / 32];

    for (int i = threadIdx.x; i < TBL_TOTAL; i += NTHR)
        s_tbl[i] = g_tbl[i];
    if (threadIdx.x < 5) {
        int k = threadIdx.x;
        s_cw[k] = cw[k];
        float4 c;
        c.x = (0 < k) ? 768.f : 2304.f;
        c.y = (1 < k) ? 768.f : 2304.f;
        c.z = (2 < k) ? 768.f : 2304.f;
        c.w = (3 < k) ? 768.f : 2304.f;
        s_c5[k] = c;
        if (k < 4) s_c4[k] = c;
    }
    __syncthreads();

    float a0 = 0.f, a1 = 0.f, a2 = 0.f;
    const int stride = gridDim.x * NTHR;
    #pragma unroll 4
    for (int i = blockIdx.x * NTHR + threadIdx.x; i < n; i += stride) {
        int kt = kt_[i];
        int mt = mt_[i];
        int lt = lt_[i];
        float4 x = kl4[i];
        float m0 = jm[3 * i], m1 = jm[3 * i + 1], m2 = jm[3 * i + 2];
        float l0 = jl[3 * i], l1 = jl[3 * i + 1], l2 = jl[3 * i + 2];

        float4 cc = s_c5[kt];
        float rk;
        rk  = tbl_eval(s_tbl, x.x, cc.x);
        rk += tbl_eval(s_tbl, x.y, cc.y);
        rk += tbl_eval(s_tbl, x.z, cc.z);
        rk += tbl_eval(s_tbl, x.w, cc.w);

        cc = s_c4[mt];
        float rm;
        rm  = tbl_eval(s_tbl, m0, cc.x);
        rm += tbl_eval(s_tbl, m1, cc.y);
        rm += tbl_eval(s_tbl, m2, cc.z);

        cc = s_c4[lt];
        float rl;
        rl  = tbl_eval(s_tbl, l0, cc.x);
        rl += tbl_eval(s_tbl, l1, cc.y);
        rl += tbl_eval(s_tbl, l2, cc.z);

        float w = s_cw[kt];
        a0 = fmaf(w, rk, a0);
        a1 = fmaf(w, rm, a1);
        a2 = fmaf(w, rl, a2);
    }

    // warp reduce
    #pragma unroll
    for (int off = 16; off > 0; off >>= 1) {
        a0 += __shfl_down_sync(0xFFFFFFFFu, a0, off);
        a1 += __shfl_down_sync(0xFFFFFFFFu, a1, off);
        a2 += __shfl_down_sync(0xFFFFFFFFu, a2, off);
    }
    int lane = threadIdx.x & 31;
    int wid  = threadIdx.x >> 5;
    if (lane == 0) {
        s_red[0][wid] = a0;
        s_red[1][wid] = a1;
        s_red[2][wid] = a2;
    }
    __syncthreads();
    if (wid == 0) {
        const int nw = NTHR / 32;
        a0 = (lane < nw) ? s_red[0][lane] : 0.f;
        a1 = (lane < nw) ? s_red[1][lane] : 0.f;
        a2 = (lane < nw) ? s_red[2][lane] : 0.f;
        #pragma unroll
        for (int off = nw / 2; off > 0; off >>= 1) {
            a0 += __shfl_down_sync(0xFFFFFFFFu, a0, off);
            a1 += __shfl_down_sync(0xFFFFFFFFu, a1, off);
            a2 += __shfl_down_sync(0xFFFFFFFFu, a2, off);
        }
        if (lane == 0) {
            atomicAdd(&g_acc[0], (double)a0);
            atomicAdd(&g_acc[1], (double)a1);
            atomicAdd(&g_acc[2], (double)a2);
            __threadfence();
            unsigned int prev = atomicAdd(&g_done, 1u);
            if (prev == gridDim.x - 1) {
                // last block: all g_acc atomics are visible (fence + atomic order)
                double lkl = g_acc[0] / (4.0 * (double)n);
                double lm  = g_acc[1] / (3.0 * (double)n);
                double ll  = g_acc[2] / (3.0 * (double)n);
                double tot = (lkl + lm + ll) / 3.0;
                if (out_size > 0) out[0] = (float)tot;
                if (out_size > 1) out[1] = (float)lkl;
                if (out_size > 2) out[2] = (float)lm;
                if (out_size > 3) out[3] = (float)ll;
            }
        }
    }
}

extern "C" void kernel_launch(void* const* d_in, const int* in_sizes, int n_in,
                              void* d_out, int out_size) {
    const float4* kl4 = (const float4*)d_in[0];   // [N,4] f32
    const float*  jm  = (const float*)d_in[1];    // [N,3] f32
    const float*  jl  = (const float*)d_in[2];    // [N,3] f32
    const float*  cw  = (const float*)d_in[3];    // [5]   f32
    const int*    kt  = (const int*)d_in[4];      // [N]   i32
    const int*    mt  = (const int*)d_in[5];      // [N]   i32
    const int*    lt  = (const int*)d_in[6];      // [N]   i32
    int n = in_sizes[4];

    init_kernel<<<(TBL_TOTAL + 255) / 256, 256>>>();
    loss_kernel<<<NBLK, NTHR>>>(kl4, jm, jl, cw, kt, mt, lt, n,
                                (float*)d_out, out_size);
}